// round 2
// baseline (speedup 1.0000x reference)
#include <cuda_runtime.h>
#include <cuda_bf16.h>
#include <mma.h>

using namespace nvcuda;

#define BATCH 65536
#define KDIM  784      // 28*28, conv folded into GEMM
#define NDIM  256
#define OUTD  10

#define BM 128
#define BN 256
#define BK 16
#define XLD 24         // smem ld for x tiles (pad, 48B = mult of 16B)
#define WLD 264        // smem ld for w tiles (pad, 528B = mult of 16B)

// Scratch (allocation-free rule: device globals)
__device__ __nv_bfloat16 g_Whi[KDIM * NDIM];
__device__ __nv_bfloat16 g_Wlo[KDIM * NDIM];
__device__ float         g_hpre[(size_t)BATCH * NDIM];

// ---------------------------------------------------------------------------
// Kernel 1: fold conv into W1_eff = C^T * w1, split into bf16 hi/lo.
// W1_eff[q][n] = sum_{i,j} [0<=r-i<26][0<=c-j<26] w_conv[i,j] * w1[(r-i)*26+(c-j)][n]
// with q = r*28 + c.
// ---------------------------------------------------------------------------
__global__ void prep_kernel(const float* __restrict__ w_conv,
                            const float* __restrict__ w1) {
    int q = blockIdx.x;        // 0..783
    int n = threadIdx.x;       // 0..255
    int r = q / 28, c = q % 28;
    float s = 0.f;
#pragma unroll
    for (int i = 0; i < 3; i++) {
        int pr = r - i;
        if (pr < 0 || pr >= 26) continue;
#pragma unroll
        for (int j = 0; j < 3; j++) {
            int pc = c - j;
            if (pc < 0 || pc >= 26) continue;
            s += w_conv[i * 3 + j] * w1[(pr * 26 + pc) * NDIM + n];
        }
    }
    __nv_bfloat16 hi = __float2bfloat16(s);
    float rem = s - __bfloat162float(hi);
    g_Whi[q * NDIM + n] = hi;
    g_Wlo[q * NDIM + n] = __float2bfloat16(rem);
}

// ---------------------------------------------------------------------------
// Kernel 2: h_pre = x @ W1_eff via split-bf16 wmma (hi*hi + hi*lo + lo*hi),
// fp32 accumulate. Block tile 128x256, 16 warps each 32x64.
// x converted fp32 -> (hi, lo) bf16 while staging into smem.
// ---------------------------------------------------------------------------
__global__ __launch_bounds__(512) void gemm_kernel(const float* __restrict__ x) {
    __shared__ __nv_bfloat16 s_xh[BM * XLD];
    __shared__ __nv_bfloat16 s_xl[BM * XLD];
    __shared__ __nv_bfloat16 s_wh[BK * WLD];
    __shared__ __nv_bfloat16 s_wl[BK * WLD];

    int tid   = threadIdx.x;
    int warp  = tid >> 5;
    int warpM = warp >> 2;     // 0..3 (rows of 32)
    int warpN = warp & 3;      // 0..3 (cols of 64)
    int rowBase = blockIdx.x * BM;

    wmma::fragment<wmma::accumulator, 16, 16, 16, float> acc[2][4];
#pragma unroll
    for (int mi = 0; mi < 2; mi++)
#pragma unroll
        for (int ni = 0; ni < 4; ni++)
            wmma::fill_fragment(acc[mi][ni], 0.0f);

    // loader lanes
    int xr = tid >> 2;           // 0..127
    int xk = (tid & 3) * 4;      // 0,4,8,12
    int wr = tid >> 5;           // 0..15
    int wn = (tid & 31) * 8;     // 0..248

    for (int k0 = 0; k0 < KDIM; k0 += BK) {
        __syncthreads();   // smem from previous iter consumed
        // ---- stage x (fp32 -> bf16 hi/lo) ----
        float4 v = *reinterpret_cast<const float4*>(
            x + (size_t)(rowBase + xr) * KDIM + k0 + xk);
        float xs[4] = {v.x, v.y, v.z, v.w};
#pragma unroll
        for (int e = 0; e < 4; e++) {
            __nv_bfloat16 hi = __float2bfloat16(xs[e]);
            s_xh[xr * XLD + xk + e] = hi;
            s_xl[xr * XLD + xk + e] = __float2bfloat16(xs[e] - __bfloat162float(hi));
        }
        // ---- stage W hi/lo (bf16, L2-resident) ----
        *reinterpret_cast<uint4*>(&s_wh[wr * WLD + wn]) =
            *reinterpret_cast<const uint4*>(&g_Whi[(size_t)(k0 + wr) * NDIM + wn]);
        *reinterpret_cast<uint4*>(&s_wl[wr * WLD + wn]) =
            *reinterpret_cast<const uint4*>(&g_Wlo[(size_t)(k0 + wr) * NDIM + wn]);
        __syncthreads();

        wmma::fragment<wmma::matrix_a, 16, 16, 16, __nv_bfloat16, wmma::row_major> ah[2], al[2];
#pragma unroll
        for (int mi = 0; mi < 2; mi++) {
            wmma::load_matrix_sync(ah[mi], s_xh + (warpM * 32 + mi * 16) * XLD, XLD);
            wmma::load_matrix_sync(al[mi], s_xl + (warpM * 32 + mi * 16) * XLD, XLD);
        }
#pragma unroll
        for (int ni = 0; ni < 4; ni++) {
            wmma::fragment<wmma::matrix_b, 16, 16, 16, __nv_bfloat16, wmma::row_major> bh, bl;
            wmma::load_matrix_sync(bh, s_wh + warpN * 64 + ni * 16, WLD);
            wmma::load_matrix_sync(bl, s_wl + warpN * 64 + ni * 16, WLD);
#pragma unroll
            for (int mi = 0; mi < 2; mi++) {
                wmma::mma_sync(acc[mi][ni], ah[mi], bh, acc[mi][ni]);
                wmma::mma_sync(acc[mi][ni], ah[mi], bl, acc[mi][ni]);
                wmma::mma_sync(acc[mi][ni], al[mi], bh, acc[mi][ni]);
            }
        }
    }

    // ---- store h_pre (pre-bias, pre-relu) ----
#pragma unroll
    for (int mi = 0; mi < 2; mi++)
#pragma unroll
        for (int ni = 0; ni < 4; ni++) {
            float* p = g_hpre +
                (size_t)(rowBase + warpM * 32 + mi * 16) * NDIM + warpN * 64 + ni * 16;
            wmma::store_matrix_sync(p, acc[mi][ni], NDIM, wmma::mem_row_major);
        }
}

// ---------------------------------------------------------------------------
// Kernel 3: out = relu(h_pre + b1) @ w2 + b2.  One warp per batch row.
// ---------------------------------------------------------------------------
__global__ __launch_bounds__(256) void head_kernel(const float* __restrict__ b1,
                                                   const float* __restrict__ w2,
                                                   const float* __restrict__ b2,
                                                   float* __restrict__ out) {
    int row  = blockIdx.x * 8 + (threadIdx.x >> 5);
    int lane = threadIdx.x & 31;
    if (row >= BATCH) return;

    const float* hrow = g_hpre + (size_t)row * NDIM;
    float acc[OUTD];
#pragma unroll
    for (int j = 0; j < OUTD; j++) acc[j] = 0.f;

#pragma unroll
    for (int i = 0; i < NDIM / 32; i++) {
        int k = lane + i * 32;
        float v = fmaxf(hrow[k] + __ldg(&b1[k]), 0.f);
#pragma unroll
        for (int j = 0; j < OUTD; j++) acc[j] += v * __ldg(&w2[k * OUTD + j]);
    }
#pragma unroll
    for (int j = 0; j < OUTD; j++) {
#pragma unroll
        for (int off = 16; off; off >>= 1)
            acc[j] += __shfl_xor_sync(0xffffffffu, acc[j], off);
    }
    if (lane < OUTD) {
        float r = 0.f;
#pragma unroll
        for (int j = 0; j < OUTD; j++) r = (j == lane) ? acc[j] : r;
        out[(size_t)row * OUTD + lane] = r + __ldg(&b2[lane]);
    }
}

// ---------------------------------------------------------------------------
extern "C" void kernel_launch(void* const* d_in, const int* in_sizes, int n_in,
                              void* d_out, int out_size) {
    const float* x      = (const float*)d_in[0];
    const float* w_conv = (const float*)d_in[1];
    const float* w1     = (const float*)d_in[2];
    const float* b1     = (const float*)d_in[3];
    const float* w2     = (const float*)d_in[4];
    const float* b2     = (const float*)d_in[5];
    float* out = (float*)d_out;

    prep_kernel<<<KDIM, NDIM>>>(w_conv, w1);
    gemm_kernel<<<BATCH / BM, 512>>>(x);
    head_kernel<<<BATCH / 8, 256>>>(b1, w2, b2, out);
}

// round 8
// speedup vs baseline: 1.1051x; 1.1051x over previous
#include <cuda_runtime.h>
#include <cuda_bf16.h>
#include <mma.h>

using namespace nvcuda;

#define BATCH 65536
#define KDIM  784      // 28*28, conv folded into GEMM (49 * 16)
#define NDIM  256
#define OUTD  10

#define BM 128
#define BK 16
#define NITER (KDIM / BK)   // 49
#define XLD 24              // smem ld (elems) for x tiles (48B, mult of 16B)
#define WLD 264             // smem ld (elems) for w tiles (528B, mult of 16B)
#define THREADS 512
#define DEC_LD 20           // epilogue decode ld in floats (80B, mult of 16B)

// Persistent weights (allocation-free rule: device globals)
__device__ __nv_bfloat16 g_Whi[KDIM * NDIM];
__device__ __nv_bfloat16 g_Wlo[KDIM * NDIM];

// ---------------------------------------------------------------------------
// Kernel 1: fold conv into W1_eff = C^T * w1, split into bf16 hi/lo.
// ---------------------------------------------------------------------------
__global__ void prep_kernel(const float* __restrict__ w_conv,
                            const float* __restrict__ w1) {
    int q = blockIdx.x;        // 0..783
    int n = threadIdx.x;       // 0..255
    int r = q / 28, c = q % 28;
    float s = 0.f;
#pragma unroll
    for (int i = 0; i < 3; i++) {
        int pr = r - i;
        if (pr < 0 || pr >= 26) continue;
#pragma unroll
        for (int j = 0; j < 3; j++) {
            int pc = c - j;
            if (pc < 0 || pc >= 26) continue;
            s += w_conv[i * 3 + j] * w1[(pr * 26 + pc) * NDIM + n];
        }
    }
    __nv_bfloat16 hi = __float2bfloat16(s);
    g_Whi[q * NDIM + n] = hi;
    g_Wlo[q * NDIM + n] = __float2bfloat16(s - __bfloat162float(hi));
}

// ---------------------------------------------------------------------------
// Fused kernel: h = relu(x @ W1_eff + b1); out = h @ w2 + b2.
// Split-bf16 wmma (hi*hi + hi*lo + lo*hi), fp32 accumulate.
// Block tile 128x256 (full N), 16 warps each 32x64.
// Ping-pong smem, register prefetch, 1 barrier per K-step.
// ---------------------------------------------------------------------------

// dynamic smem layout (bf16 elems):
//   xh[2][BM*XLD], xl[2][BM*XLD], wh[2][BK*WLD], wl[2][BK*WLD]
#define XBUF (BM * XLD)            // 3072 elems
#define WBUF (BK * WLD)            // 4224 elems
#define SM_XH(b) (smb + (b) * XBUF)
#define SM_XL(b) (smb + 2 * XBUF + (b) * XBUF)
#define SM_WH(b) (smb + 4 * XBUF + (b) * WBUF)
#define SM_WL(b) (smb + 4 * XBUF + 2 * WBUF + (b) * WBUF)
#define SMEM_BYTES ((4 * XBUF + 4 * WBUF) * 2)   // 58368 B

extern "C" __global__ void __launch_bounds__(THREADS, 1)
fused_kernel(const float* __restrict__ x,
             const float* __restrict__ b1,
             const float* __restrict__ w2,
             const float* __restrict__ b2,
             float* __restrict__ out) {
    extern __shared__ __nv_bfloat16 smb[];

    int tid   = threadIdx.x;
    int warp  = tid >> 5;
    int lane  = tid & 31;
    int warpM = warp >> 2;     // 0..3
    int warpN = warp & 3;      // 0..3
    int rowBase = blockIdx.x * BM;

    wmma::fragment<wmma::accumulator, 16, 16, 16, float> acc[2][4];
#pragma unroll
    for (int mi = 0; mi < 2; mi++)
#pragma unroll
        for (int ni = 0; ni < 4; ni++)
            wmma::fill_fragment(acc[mi][ni], 0.0f);

    // loader lane mapping
    int xr = tid >> 2;           // 0..127 (x row)
    int xk = (tid & 3) * 4;      // 0,4,8,12
    int wr = tid >> 5;           // 0..15  (w row)
    int wn = (tid & 31) * 8;     // 0..248

    const float* xptr = x + (size_t)(rowBase + xr) * KDIM + xk;

    // ---- prologue: load tile 0, stage into buf 0 ----
    float4 vx = *reinterpret_cast<const float4*>(xptr);
    uint4 vwh = *reinterpret_cast<const uint4*>(&g_Whi[(size_t)wr * NDIM + wn]);
    uint4 vwl = *reinterpret_cast<const uint4*>(&g_Wlo[(size_t)wr * NDIM + wn]);
    {
        float xs[4] = {vx.x, vx.y, vx.z, vx.w};
#pragma unroll
        for (int e = 0; e < 4; e++) {
            __nv_bfloat16 hi = __float2bfloat16(xs[e]);
            SM_XH(0)[xr * XLD + xk + e] = hi;
            SM_XL(0)[xr * XLD + xk + e] = __float2bfloat16(xs[e] - __bfloat162float(hi));
        }
        *reinterpret_cast<uint4*>(&SM_WH(0)[wr * WLD + wn]) = vwh;
        *reinterpret_cast<uint4*>(&SM_WL(0)[wr * WLD + wn]) = vwl;
    }
    __syncthreads();

    for (int it = 0; it < NITER; it++) {
        int cur = it & 1;
        // ---- prefetch next tile into registers ----
        if (it + 1 < NITER) {
            int k0 = (it + 1) * BK;
            vx  = *reinterpret_cast<const float4*>(xptr + k0);
            vwh = *reinterpret_cast<const uint4*>(&g_Whi[(size_t)(k0 + wr) * NDIM + wn]);
            vwl = *reinterpret_cast<const uint4*>(&g_Wlo[(size_t)(k0 + wr) * NDIM + wn]);
        }

        // ---- compute on current buffer ----
        wmma::fragment<wmma::matrix_a, 16, 16, 16, __nv_bfloat16, wmma::row_major> ah[2], al[2];
#pragma unroll
        for (int mi = 0; mi < 2; mi++) {
            wmma::load_matrix_sync(ah[mi], SM_XH(cur) + (warpM * 32 + mi * 16) * XLD, XLD);
            wmma::load_matrix_sync(al[mi], SM_XL(cur) + (warpM * 32 + mi * 16) * XLD, XLD);
        }
#pragma unroll
        for (int ni = 0; ni < 4; ni++) {
            wmma::fragment<wmma::matrix_b, 16, 16, 16, __nv_bfloat16, wmma::row_major> bh, bl;
            wmma::load_matrix_sync(bh, SM_WH(cur) + warpN * 64 + ni * 16, WLD);
            wmma::load_matrix_sync(bl, SM_WL(cur) + warpN * 64 + ni * 16, WLD);
#pragma unroll
            for (int mi = 0; mi < 2; mi++) {
                wmma::mma_sync(acc[mi][ni], ah[mi], bh, acc[mi][ni]);
                wmma::mma_sync(acc[mi][ni], ah[mi], bl, acc[mi][ni]);
                wmma::mma_sync(acc[mi][ni], al[mi], bh, acc[mi][ni]);
            }
        }

        // ---- stage prefetched tile into other buffer ----
        if (it + 1 < NITER) {
            int nxt = cur ^ 1;
            float xs[4] = {vx.x, vx.y, vx.z, vx.w};
#pragma unroll
            for (int e = 0; e < 4; e++) {
                __nv_bfloat16 hi = __float2bfloat16(xs[e]);
                SM_XH(nxt)[xr * XLD + xk + e] = hi;
                SM_XL(nxt)[xr * XLD + xk + e] = __float2bfloat16(xs[e] - __bfloat162float(hi));
            }
            *reinterpret_cast<uint4*>(&SM_WH(nxt)[wr * WLD + wn]) = vwh;
            *reinterpret_cast<uint4*>(&SM_WL(nxt)[wr * WLD + wn]) = vwl;
        }
        __syncthreads();
    }

    // ======================= fused epilogue =======================
    // alias smem (all pipeline reads done; last __syncthreads above):
    //   dec  : per-warp 16 x DEC_LD float strips  [16 * 320 floats]
    //   s_out: 128 x 12 float                     [1536 floats]
    float* smf   = reinterpret_cast<float*>(smb);
    float* dec   = smf + warp * (16 * DEC_LD);
    float* s_out = smf + 16 * (16 * DEC_LD);

    // zero s_out (pre-b2 accumulator)
    for (int i = tid; i < BM * OUTD; i += THREADS) {
        int r = i / OUTD, j = i % OUTD;
        s_out[r * 12 + j] = 0.f;
    }
    __syncthreads();

    int rhalf = lane & 15;            // row within frag
    int chalf = (lane >> 4) * 8;      // col half: 0 or 8
#pragma unroll
    for (int mi = 0; mi < 2; mi++) {
#pragma unroll
        for (int ni = 0; ni < 4; ni++) {
            wmma::store_matrix_sync(dec, acc[mi][ni], DEC_LD, wmma::mem_row_major);
            __syncwarp();
            int row = warpM * 32 + mi * 16 + rhalf;
            float p[OUTD];
#pragma unroll
            for (int j = 0; j < OUTD; j++) p[j] = 0.f;
#pragma unroll
            for (int c = 0; c < 8; c++) {
                int n = warpN * 64 + ni * 16 + chalf + c;
                float v = dec[rhalf * DEC_LD + chalf + c] + __ldg(&b1[n]);
                v = fmaxf(v, 0.f);
#pragma unroll
                for (int j = 0; j < OUTD; j++)
                    p[j] += v * __ldg(&w2[n * OUTD + j]);
            }
#pragma unroll
            for (int j = 0; j < OUTD; j++)
                atomicAdd(&s_out[row * 12 + j], p[j]);
            __syncwarp();
        }
    }
    __syncthreads();

    // write out (+ b2)
    for (int i = tid; i < BM * OUTD; i += THREADS) {
        int r = i / OUTD, j = i % OUTD;
        out[(size_t)(rowBase + r) * OUTD + j] = s_out[r * 12 + j] + __ldg(&b2[j]);
    }
}

// ---------------------------------------------------------------------------
extern "C" void kernel_launch(void* const* d_in, const int* in_sizes, int n_in,
                              void* d_out, int out_size) {
    const float* x      = (const float*)d_in[0];
    const float* w_conv = (const float*)d_in[1];
    const float* w1     = (const float*)d_in[2];
    const float* b1     = (const float*)d_in[3];
    const float* w2     = (const float*)d_in[4];
    const float* b2     = (const float*)d_in[5];
    float* out = (float*)d_out;

    cudaFuncSetAttribute(fused_kernel,
                         cudaFuncAttributeMaxDynamicSharedMemorySize,
                         SMEM_BYTES);

    prep_kernel<<<KDIM, NDIM>>>(w_conv, w1);
    fused_kernel<<<BATCH / BM, THREADS, SMEM_BYTES>>>(x, b1, w2, b2, out);
}

// round 11
// speedup vs baseline: 1.1692x; 1.0580x over previous
#include <cuda_runtime.h>
#include <cuda_bf16.h>
#include <mma.h>

using namespace nvcuda;

#define BATCH 65536
#define KDIM  784
#define NDIM  256
#define OUTD  10

#define BM 128
#define BN 128              // N-half per CTA
#define BK 16
#define NITER (KDIM / BK)   // 49
#define XLD 24              // smem ld (elems) x tiles (48B)
#define WLD 136             // smem ld (elems) w tiles (272B)
#define THREADS 256
#define DEC_LD 20           // decode ld (80B)

// ---- smem layout (bytes) ----
#define XH_OFF(b) ((b) * 6144)
#define XL_OFF(b) (12288 + (b) * 6144)
#define WH_OFF(b) (24576 + (b) * 4352)
#define WL_OFF(b) (33280 + (b) * 4352)
#define SP_OFF    41984               // s_part 128*12 f = 6144
#define B1_OFF    48128               // 128 f
#define W2_OFF    48640               // 128*12 f = 6144
#define SMEM_BYTES 54784

// Persistent weights + cross-CTA partials (allocation-free rule: device globals)
__device__ __nv_bfloat16 g_Whi[KDIM * NDIM];
__device__ __nv_bfloat16 g_Wlo[KDIM * NDIM];
__device__ float g_part[2][(size_t)BATCH * 12];

// ---------------------------------------------------------------------------
// prep: fold conv into W1_eff = C^T * w1, split into bf16 hi/lo.
// ---------------------------------------------------------------------------
__global__ void prep_kernel(const float* __restrict__ w_conv,
                            const float* __restrict__ w1) {
    int q = blockIdx.x;        // 0..783
    int n = threadIdx.x;       // 0..255
    int r = q / 28, c = q % 28;
    float s = 0.f;
#pragma unroll
    for (int i = 0; i < 3; i++) {
        int pr = r - i;
        if (pr < 0 || pr >= 26) continue;
#pragma unroll
        for (int j = 0; j < 3; j++) {
            int pc = c - j;
            if (pc < 0 || pc >= 26) continue;
            s += w_conv[i * 3 + j] * w1[(pr * 26 + pc) * NDIM + n];
        }
    }
    __nv_bfloat16 hi = __float2bfloat16(s);
    g_Whi[q * NDIM + n] = hi;
    g_Wlo[q * NDIM + n] = __float2bfloat16(s - __bfloat162float(hi));
}

// ---------------------------------------------------------------------------
// GEMM half-kernel: partial = relu(x @ W1_eff[:, half] + b1[half]) @ w2[half]
// Block 128x128, 8 warps (4x2), warp tile 32x64, ping-pong smem.
// ---------------------------------------------------------------------------
extern "C" __global__ void __launch_bounds__(THREADS, 2)
gemm_half_kernel(const float* __restrict__ x,
                 const float* __restrict__ b1,
                 const float* __restrict__ w2) {
    extern __shared__ __align__(128) char sm[];

    int tid   = threadIdx.x;
    int warp  = tid >> 5;
    int lane  = tid & 31;
    int warpM = warp >> 1;               // 0..3
    int warpN = warp & 1;                // 0..1
    int half    = blockIdx.x;            // 0..1  (fastest -> x tile L2 reuse)
    int rowBase = blockIdx.y * BM;
    int nBase   = half * BN;

    float* s_part = reinterpret_cast<float*>(sm + SP_OFF);
    float* s_b1   = reinterpret_cast<float*>(sm + B1_OFF);
    float* s_w2   = reinterpret_cast<float*>(sm + W2_OFF);

    // ---- init epilogue constants + partial accumulator ----
    for (int i = tid; i < BN; i += THREADS) s_b1[i] = b1[nBase + i];
    for (int i = tid; i < BN; i += THREADS) {
#pragma unroll
        for (int j = 0; j < OUTD; j++) s_w2[i * 12 + j] = w2[(nBase + i) * OUTD + j];
        s_w2[i * 12 + 10] = 0.f; s_w2[i * 12 + 11] = 0.f;
    }
    for (int i = tid; i < BM * 12; i += THREADS) s_part[i] = 0.f;

    wmma::fragment<wmma::accumulator, 16, 16, 16, float> acc[2][4];
#pragma unroll
    for (int mi = 0; mi < 2; mi++)
#pragma unroll
        for (int ni = 0; ni < 4; ni++)
            wmma::fill_fragment(acc[mi][ni], 0.0f);

    // loader mapping
    int xr  = tid >> 1;            // 0..127
    int xc  = (tid & 1) * 8;       // 0 or 8
    int wr  = tid >> 4;            // 0..15
    int wc  = (tid & 15) * 8;      // 0..120

    const float* xptr = x + (size_t)(rowBase + xr) * KDIM + xc;
    const __nv_bfloat16* whp = g_Whi + (size_t)wr * NDIM + nBase + wc;
    const __nv_bfloat16* wlp = g_Wlo + (size_t)wr * NDIM + nBase + wc;

    // ---- prologue: stage block 0 into buf 0 ----
    float4 vx0 = *reinterpret_cast<const float4*>(xptr);
    float4 vx1 = *reinterpret_cast<const float4*>(xptr + 4);
    uint4  vwh = *reinterpret_cast<const uint4*>(whp);
    uint4  vwl = *reinterpret_cast<const uint4*>(wlp);
    {
        float xs[8] = {vx0.x, vx0.y, vx0.z, vx0.w, vx1.x, vx1.y, vx1.z, vx1.w};
        __nv_bfloat16 hb[8], lb[8];
#pragma unroll
        for (int e = 0; e < 8; e++) {
            __nv_bfloat16 h = __float2bfloat16(xs[e]);
            hb[e] = h;
            lb[e] = __float2bfloat16(xs[e] - __bfloat162float(h));
        }
        *reinterpret_cast<uint4*>(sm + XH_OFF(0) + (xr * XLD + xc) * 2) = *reinterpret_cast<uint4*>(hb);
        *reinterpret_cast<uint4*>(sm + XL_OFF(0) + (xr * XLD + xc) * 2) = *reinterpret_cast<uint4*>(lb);
        *reinterpret_cast<uint4*>(sm + WH_OFF(0) + (wr * WLD + wc) * 2) = vwh;
        *reinterpret_cast<uint4*>(sm + WL_OFF(0) + (wr * WLD + wc) * 2) = vwl;
    }
    __syncthreads();

    for (int it = 0; it < NITER; it++) {
        int cur = it & 1;
        if (it + 1 < NITER) {
            int k0 = (it + 1) * BK;
            vx0 = *reinterpret_cast<const float4*>(xptr + k0);
            vx1 = *reinterpret_cast<const float4*>(xptr + k0 + 4);
            vwh = *reinterpret_cast<const uint4*>(whp + (size_t)k0 * NDIM);
            vwl = *reinterpret_cast<const uint4*>(wlp + (size_t)k0 * NDIM);
        }

        // ---- compute on current buffer ----
        {
            const __nv_bfloat16* xh = reinterpret_cast<const __nv_bfloat16*>(sm + XH_OFF(cur));
            const __nv_bfloat16* xl = reinterpret_cast<const __nv_bfloat16*>(sm + XL_OFF(cur));
            const __nv_bfloat16* wh = reinterpret_cast<const __nv_bfloat16*>(sm + WH_OFF(cur));
            const __nv_bfloat16* wl = reinterpret_cast<const __nv_bfloat16*>(sm + WL_OFF(cur));
            wmma::fragment<wmma::matrix_a, 16, 16, 16, __nv_bfloat16, wmma::row_major> ah[2], al[2];
#pragma unroll
            for (int mi = 0; mi < 2; mi++) {
                wmma::load_matrix_sync(ah[mi], xh + (warpM * 32 + mi * 16) * XLD, XLD);
                wmma::load_matrix_sync(al[mi], xl + (warpM * 32 + mi * 16) * XLD, XLD);
            }
#pragma unroll
            for (int ni = 0; ni < 4; ni++) {
                wmma::fragment<wmma::matrix_b, 16, 16, 16, __nv_bfloat16, wmma::row_major> bh, bl;
                wmma::load_matrix_sync(bh, wh + warpN * 64 + ni * 16, WLD);
                wmma::load_matrix_sync(bl, wl + warpN * 64 + ni * 16, WLD);
#pragma unroll
                for (int mi = 0; mi < 2; mi++) {
                    wmma::mma_sync(acc[mi][ni], ah[mi], bh, acc[mi][ni]);
                    wmma::mma_sync(acc[mi][ni], ah[mi], bl, acc[mi][ni]);
                    wmma::mma_sync(acc[mi][ni], al[mi], bh, acc[mi][ni]);
                }
            }
        }

        // ---- stage prefetched into other buffer ----
        if (it + 1 < NITER) {
            int nxt = cur ^ 1;
            float xs[8] = {vx0.x, vx0.y, vx0.z, vx0.w, vx1.x, vx1.y, vx1.z, vx1.w};
            __nv_bfloat16 hb[8], lb[8];
#pragma unroll
            for (int e = 0; e < 8; e++) {
                __nv_bfloat16 h = __float2bfloat16(xs[e]);
                hb[e] = h;
                lb[e] = __float2bfloat16(xs[e] - __bfloat162float(h));
            }
            *reinterpret_cast<uint4*>(sm + XH_OFF(nxt) + (xr * XLD + xc) * 2) = *reinterpret_cast<uint4*>(hb);
            *reinterpret_cast<uint4*>(sm + XL_OFF(nxt) + (xr * XLD + xc) * 2) = *reinterpret_cast<uint4*>(lb);
            *reinterpret_cast<uint4*>(sm + WH_OFF(nxt) + (wr * WLD + wc) * 2) = vwh;
            *reinterpret_cast<uint4*>(sm + WL_OFF(nxt) + (wr * WLD + wc) * 2) = vwl;
        }
        __syncthreads();
    }

    // ======================= epilogue =======================
    // dec strips alias the tile region (mainloop fully consumed after last sync)
    float* dec = reinterpret_cast<float*>(sm) + warp * (16 * DEC_LD);

    int rhalf = lane & 15;
    int chalf = (lane >> 4) * 8;
#pragma unroll
    for (int mi = 0; mi < 2; mi++) {
#pragma unroll
        for (int ni = 0; ni < 4; ni++) {
            wmma::store_matrix_sync(dec, acc[mi][ni], DEC_LD, wmma::mem_row_major);
            __syncwarp();
            int row = warpM * 32 + mi * 16 + rhalf;
            float p[OUTD];
#pragma unroll
            for (int j = 0; j < OUTD; j++) p[j] = 0.f;
#pragma unroll
            for (int c = 0; c < 8; c++) {
                int n = warpN * 64 + ni * 16 + chalf + c;   // 0..127 (local)
                float v = dec[rhalf * DEC_LD + chalf + c] + s_b1[n];
                v = fmaxf(v, 0.f);
#pragma unroll
                for (int j = 0; j < OUTD; j++)
                    p[j] += v * s_w2[n * 12 + j];
            }
#pragma unroll
            for (int j = 0; j < OUTD; j++)
                atomicAdd(&s_part[row * 12 + j], p[j]);
            __syncwarp();
        }
    }
    __syncthreads();

    // write partials to global (per-half buffer; summed by sum_kernel)
    float* gp = g_part[half] + (size_t)rowBase * 12;
    for (int i = tid; i < BM * 12; i += THREADS)
        gp[i] = s_part[i];
}

// ---------------------------------------------------------------------------
// sum: out = part0 + part1 + b2   (deterministic cross-half reduction)
// ---------------------------------------------------------------------------
__global__ void __launch_bounds__(256)
sum_kernel(const float* __restrict__ b2, float* __restrict__ out) {
    int i = blockIdx.x * 256 + threadIdx.x;
    if (i >= BATCH * OUTD) return;
    int r = i / OUTD, j = i - r * OUTD;
    out[i] = g_part[0][(size_t)r * 12 + j] + g_part[1][(size_t)r * 12 + j] + b2[j];
}

// ---------------------------------------------------------------------------
extern "C" void kernel_launch(void* const* d_in, const int* in_sizes, int n_in,
                              void* d_out, int out_size) {
    const float* x      = (const float*)d_in[0];
    const float* w_conv = (const float*)d_in[1];
    const float* w1     = (const float*)d_in[2];
    const float* b1     = (const float*)d_in[3];
    const float* w2     = (const float*)d_in[4];
    const float* b2     = (const float*)d_in[5];
    float* out = (float*)d_out;

    cudaFuncSetAttribute(gemm_half_kernel,
                         cudaFuncAttributeMaxDynamicSharedMemorySize, SMEM_BYTES);

    prep_kernel<<<KDIM, NDIM>>>(w_conv, w1);
    gemm_half_kernel<<<dim3(2, BATCH / BM), THREADS, SMEM_BYTES>>>(x, b1, w2);
    sum_kernel<<<(BATCH * OUTD + 255) / 256, 256>>>(b2, out);
}

// round 13
// speedup vs baseline: 1.3209x; 1.1297x over previous
#include <cuda_runtime.h>
#include <cuda_bf16.h>
#include <mma.h>
#include <cstdint>

using namespace nvcuda;

#define BATCH 65536
#define KDIM  784
#define NDIM  256
#define OUTD  10

#define BM 128
#define BN 256
#define BK 16
#define NITER (KDIM / BK)   // 49
#define XLD 24              // x smem ld (elems), 48B rows
#define WLD 264             // w smem ld (elems), 528B rows
#define THREADS 256         // 8 warps: 2 (M) x 4 (N), warp tile 64x64
#define DEC_LD 20           // decode ld (80B)

// ---- smem layout (bytes) ----
#define XH_OFF(b) ((b) * 6144)              // 128*24*2
#define XL_OFF(b) (12288 + (b) * 6144)
#define WH_OFF(b) (24576 + (b) * 8448)      // 16*264*2
#define WL_OFF(b) (41472 + (b) * 8448)
#define SOUT_OFF  58368                     // 128*12 floats
#define B1_OFF    64512                     // 256 floats
#define W2_OFF    65536                     // 256*12 floats
#define B2_OFF    77824                     // 12 floats
#define SMEM_BYTES 77872

// Persistent weights (allocation-free rule: device globals)
__device__ __nv_bfloat16 g_Whi[KDIM * NDIM];
__device__ __nv_bfloat16 g_Wlo[KDIM * NDIM];

__device__ __forceinline__ uint32_t smem_u32(const void* p) {
    uint32_t a;
    asm("{ .reg .u64 t; cvta.to.shared.u64 t, %1; cvt.u32.u64 %0, t; }" : "=r"(a) : "l"(p));
    return a;
}
__device__ __forceinline__ void cp_async16(uint32_t dst, const void* src) {
    asm volatile("cp.async.ca.shared.global [%0], [%1], 16;" :: "r"(dst), "l"(src) : "memory");
}
#define CP_COMMIT() asm volatile("cp.async.commit_group;" ::: "memory")
#define CP_WAIT0()  asm volatile("cp.async.wait_group 0;" ::: "memory")

// ---------------------------------------------------------------------------
// prep: fold conv into W1_eff = C^T * w1, split into bf16 hi/lo.
// ---------------------------------------------------------------------------
__global__ void prep_kernel(const float* __restrict__ w_conv,
                            const float* __restrict__ w1) {
    int q = blockIdx.x;        // 0..783
    int n = threadIdx.x;       // 0..255
    int r = q / 28, c = q % 28;
    float s = 0.f;
#pragma unroll
    for (int i = 0; i < 3; i++) {
        int pr = r - i;
        if (pr < 0 || pr >= 26) continue;
#pragma unroll
        for (int j = 0; j < 3; j++) {
            int pc = c - j;
            if (pc < 0 || pc >= 26) continue;
            s += w_conv[i * 3 + j] * w1[(pr * 26 + pc) * NDIM + n];
        }
    }
    __nv_bfloat16 hi = __float2bfloat16(s);
    g_Whi[q * NDIM + n] = hi;
    g_Wlo[q * NDIM + n] = __float2bfloat16(s - __bfloat162float(hi));
}

// ---------------------------------------------------------------------------
// Fused: out = relu(x @ W1_eff + b1) @ w2 + b2
// CTA 128x256 (full N), 8 warps of 64x64, split-bf16 3-term wmma.
// Ping-pong smem; x via LDG reg-prefetch, W via cp.async.
// ---------------------------------------------------------------------------
extern "C" __global__ void __launch_bounds__(THREADS, 1)
fused_kernel(const float* __restrict__ x,
             const float* __restrict__ b1,
             const float* __restrict__ w2,
             const float* __restrict__ b2,
             float* __restrict__ out) {
    extern __shared__ __align__(128) char sm[];
    uint32_t smb = smem_u32(sm);

    int tid   = threadIdx.x;
    int warp  = tid >> 5;
    int lane  = tid & 31;
    int warpM = warp >> 2;               // 0..1 (64-row strips)
    int warpN = warp & 3;                // 0..3 (64-col strips)
    int rowBase = blockIdx.x * BM;

    float* s_out = reinterpret_cast<float*>(sm + SOUT_OFF);
    float* s_b1  = reinterpret_cast<float*>(sm + B1_OFF);
    float* s_w2  = reinterpret_cast<float*>(sm + W2_OFF);
    float* s_b2  = reinterpret_cast<float*>(sm + B2_OFF);

    // ---- epilogue constants + accumulator init ----
    for (int i = tid; i < NDIM; i += THREADS) s_b1[i] = b1[i];
    for (int i = tid; i < NDIM; i += THREADS) {
#pragma unroll
        for (int j = 0; j < OUTD; j++) s_w2[i * 12 + j] = w2[i * OUTD + j];
        s_w2[i * 12 + 10] = 0.f; s_w2[i * 12 + 11] = 0.f;
    }
    if (tid < 12) s_b2[tid] = (tid < OUTD) ? b2[tid] : 0.f;
    for (int i = tid; i < BM * 12; i += THREADS) s_out[i] = 0.f;

    wmma::fragment<wmma::accumulator, 16, 16, 16, float> acc[4][4];
#pragma unroll
    for (int mi = 0; mi < 4; mi++)
#pragma unroll
        for (int ni = 0; ni < 4; ni++)
            wmma::fill_fragment(acc[mi][ni], 0.0f);

    // loader mapping
    int xr = tid >> 1;               // 0..127
    int xc = (tid & 1) * 8;          // 0 or 8
    int wr = tid >> 4;               // 0..15
    int wc = (tid & 15) * 16;        // 0..240 (16 bf16 = 32B per array)

    const float* xptr = x + (size_t)(rowBase + xr) * KDIM + xc;
    const __nv_bfloat16* whp = g_Whi + (size_t)wr * NDIM + wc;
    const __nv_bfloat16* wlp = g_Wlo + (size_t)wr * NDIM + wc;
    uint32_t wdsth = smb + (uint32_t)(wr * WLD + wc) * 2;   // + WH_OFF(buf)
    uint32_t wdstl = smb + (uint32_t)(wr * WLD + wc) * 2;   // + WL_OFF(buf)

    auto stage_x = [&](int buf, float4 v0, float4 v1) {
        float xs[8] = {v0.x, v0.y, v0.z, v0.w, v1.x, v1.y, v1.z, v1.w};
        __nv_bfloat16 hb[8], lb[8];
#pragma unroll
        for (int e = 0; e < 8; e++) {
            __nv_bfloat16 h = __float2bfloat16(xs[e]);
            hb[e] = h;
            lb[e] = __float2bfloat16(xs[e] - __bfloat162float(h));
        }
        *reinterpret_cast<uint4*>(sm + XH_OFF(buf) + (xr * XLD + xc) * 2) = *reinterpret_cast<uint4*>(hb);
        *reinterpret_cast<uint4*>(sm + XL_OFF(buf) + (xr * XLD + xc) * 2) = *reinterpret_cast<uint4*>(lb);
    };
    auto issue_w = [&](int blk, int buf) {
        size_t off = (size_t)blk * BK * NDIM;
        cp_async16(wdsth + WH_OFF(buf),      whp + off);
        cp_async16(wdsth + WH_OFF(buf) + 16, whp + off + 8);
        cp_async16(wdstl + WL_OFF(buf),      wlp + off);
        cp_async16(wdstl + WL_OFF(buf) + 16, wlp + off + 8);
        CP_COMMIT();
    };

    // ---- prologue: stage block 0 into buf 0 ----
    issue_w(0, 0);
    {
        float4 v0 = *reinterpret_cast<const float4*>(xptr);
        float4 v1 = *reinterpret_cast<const float4*>(xptr + 4);
        stage_x(0, v0, v1);
    }
    CP_WAIT0();
    __syncthreads();

    float4 vx0, vx1;
    for (int it = 0; it < NITER; it++) {
        int cur = it & 1;
        int nxt = cur ^ 1;
        if (it + 1 < NITER) {
            int k0 = (it + 1) * BK;
            issue_w(it + 1, nxt);
            vx0 = *reinterpret_cast<const float4*>(xptr + k0);
            vx1 = *reinterpret_cast<const float4*>(xptr + k0 + 4);
        }

        // ---- compute on current buffer: warp tile 64x64, A-frags resident ----
        {
            const __nv_bfloat16* xh = reinterpret_cast<const __nv_bfloat16*>(sm + XH_OFF(cur));
            const __nv_bfloat16* xl = reinterpret_cast<const __nv_bfloat16*>(sm + XL_OFF(cur));
            const __nv_bfloat16* wh = reinterpret_cast<const __nv_bfloat16*>(sm + WH_OFF(cur));
            const __nv_bfloat16* wl = reinterpret_cast<const __nv_bfloat16*>(sm + WL_OFF(cur));

            wmma::fragment<wmma::matrix_a, 16, 16, 16, __nv_bfloat16, wmma::row_major> ah[4], al[4];
#pragma unroll
            for (int mi = 0; mi < 4; mi++) {
                wmma::load_matrix_sync(ah[mi], xh + (warpM * 64 + mi * 16) * XLD, XLD);
                wmma::load_matrix_sync(al[mi], xl + (warpM * 64 + mi * 16) * XLD, XLD);
            }
#pragma unroll
            for (int ni = 0; ni < 4; ni++) {
                wmma::fragment<wmma::matrix_b, 16, 16, 16, __nv_bfloat16, wmma::row_major> bh, bl;
                wmma::load_matrix_sync(bh, wh + warpN * 64 + ni * 16, WLD);
                wmma::load_matrix_sync(bl, wl + warpN * 64 + ni * 16, WLD);
#pragma unroll
                for (int mi = 0; mi < 4; mi++) {
                    wmma::mma_sync(acc[mi][ni], ah[mi], bh, acc[mi][ni]);
                    wmma::mma_sync(acc[mi][ni], ah[mi], bl, acc[mi][ni]);
                    wmma::mma_sync(acc[mi][ni], al[mi], bh, acc[mi][ni]);
                }
            }
        }

        if (it + 1 < NITER) {
            stage_x(nxt, vx0, vx1);
            CP_WAIT0();
        }
        __syncthreads();
    }

    // ======================= fused epilogue =======================
    // dec strips alias tile region (fully consumed after last sync): 8*1280B
    float* dec = reinterpret_cast<float*>(sm) + warp * (16 * DEC_LD);

    int rhalf = lane & 15;
    int chalf = (lane >> 4) * 8;
#pragma unroll
    for (int mi = 0; mi < 4; mi++) {
        int row = warpM * 64 + mi * 16 + rhalf;
        float p[12];
#pragma unroll
        for (int j = 0; j < 12; j++) p[j] = 0.f;
#pragma unroll
        for (int ni = 0; ni < 4; ni++) {
            wmma::store_matrix_sync(dec, acc[mi][ni], DEC_LD, wmma::mem_row_major);
            __syncwarp();
#pragma unroll
            for (int c = 0; c < 8; c++) {
                int n = warpN * 64 + ni * 16 + chalf + c;
                float v = dec[rhalf * DEC_LD + chalf + c] + s_b1[n];
                v = fmaxf(v, 0.f);
                const float4* wrp = reinterpret_cast<const float4*>(s_w2 + n * 12);
                float4 w0 = wrp[0], w1v = wrp[1], w2v = wrp[2];
                p[0]  += v * w0.x;  p[1]  += v * w0.y;  p[2]  += v * w0.z;  p[3]  += v * w0.w;
                p[4]  += v * w1v.x; p[5]  += v * w1v.y; p[6]  += v * w1v.z; p[7]  += v * w1v.w;
                p[8]  += v * w2v.x; p[9]  += v * w2v.y; p[10] += v * w2v.z; p[11] += v * w2v.w;
            }
            __syncwarp();
        }
#pragma unroll
        for (int j = 0; j < OUTD; j++)
            atomicAdd(&s_out[row * 12 + j], p[j]);
    }
    __syncthreads();

    // write out (+ b2)
    for (int i = tid; i < BM * OUTD; i += THREADS) {
        int r = i / OUTD, j = i - r * OUTD;
        out[(size_t)(rowBase + r) * OUTD + j] = s_out[r * 12 + j] + s_b2[j];
    }
}

// ---------------------------------------------------------------------------
extern "C" void kernel_launch(void* const* d_in, const int* in_sizes, int n_in,
                              void* d_out, int out_size) {
    const float* x      = (const float*)d_in[0];
    const float* w_conv = (const float*)d_in[1];
    const float* w1     = (const float*)d_in[2];
    const float* b1     = (const float*)d_in[3];
    const float* w2     = (const float*)d_in[4];
    const float* b2     = (const float*)d_in[5];
    float* out = (float*)d_out;

    cudaFuncSetAttribute(fused_kernel,
                         cudaFuncAttributeMaxDynamicSharedMemorySize, SMEM_BYTES);

    prep_kernel<<<KDIM, NDIM>>>(w_conv, w1);
    fused_kernel<<<BATCH / BM, THREADS, SMEM_BYTES>>>(x, b1, w2, b2, out);
}

// round 14
// speedup vs baseline: 1.6192x; 1.2258x over previous
#include <cuda_runtime.h>
#include <cuda_fp16.h>
#include <mma.h>
#include <cstdint>

using namespace nvcuda;

#define BATCH 65536
#define KDIM  784
#define KPAD  800           // 25 * 32, zero-padded weights
#define NDIM  256
#define OUTD  10

#define BM 128
#define BN 256
#define BK 32
#define NITER (KPAD / BK)   // 25
#define XLD 40              // x smem ld (elems), 80B rows
#define WLD 264             // w smem ld (elems), 528B rows
#define THREADS 256         // 8 warps: 2 (M) x 4 (N), warp tile 64x64
#define DEC_LD 20           // decode ld (80B)

// ---- smem layout (bytes) ----
#define XH_OFF(b) ((b) * 10240)             // 128*40*2
#define WH_OFF(b) (20480 + (b) * 16896)     // 32*264*2
#define WL_OFF(b) (54272 + (b) * 16896)
#define SOUT_OFF  88064                     // 128*12 floats
#define B1_OFF    94208                     // 256 floats
#define W2_OFF    95232                     // 256*12 floats
#define B2_OFF    107520                    // 12 floats
#define SMEM_BYTES 107568

// Persistent weights (allocation-free rule: device globals), fp16 2-term split
__device__ __half g_Wh[KPAD * NDIM];
__device__ __half g_Wl[KPAD * NDIM];

__device__ __forceinline__ uint32_t smem_u32(const void* p) {
    uint32_t a;
    asm("{ .reg .u64 t; cvta.to.shared.u64 t, %1; cvt.u32.u64 %0, t; }" : "=r"(a) : "l"(p));
    return a;
}
__device__ __forceinline__ void cp_async16(uint32_t dst, const void* src) {
    asm volatile("cp.async.ca.shared.global [%0], [%1], 16;" :: "r"(dst), "l"(src) : "memory");
}
#define CP_COMMIT() asm volatile("cp.async.commit_group;" ::: "memory")
#define CP_WAIT0()  asm volatile("cp.async.wait_group 0;" ::: "memory")

// ---------------------------------------------------------------------------
// prep: fold conv into W1_eff = C^T * w1, split into fp16 hi/lo (rows >= 784 zero)
// ---------------------------------------------------------------------------
__global__ void prep_kernel(const float* __restrict__ w_conv,
                            const float* __restrict__ w1) {
    int q = blockIdx.x;        // 0..799
    int n = threadIdx.x;       // 0..255
    float s = 0.f;
    if (q < KDIM) {
        int r = q / 28, c = q % 28;
#pragma unroll
        for (int i = 0; i < 3; i++) {
            int pr = r - i;
            if (pr < 0 || pr >= 26) continue;
#pragma unroll
            for (int j = 0; j < 3; j++) {
                int pc = c - j;
                if (pc < 0 || pc >= 26) continue;
                s += w_conv[i * 3 + j] * w1[(pr * 26 + pc) * NDIM + n];
            }
        }
    }
    __half hi = __float2half_rn(s);
    g_Wh[q * NDIM + n] = hi;
    g_Wl[q * NDIM + n] = __float2half_rn(s - __half2float(hi));
}

// ---------------------------------------------------------------------------
// Fused: out = relu(x @ W1_eff + b1) @ w2 + b2
// fp16 2-term: acc = x_h @ w_h + x_h @ w_l  (x_lo dropped, err ~1.4e-4)
// CTA 128x256 (full N), 8 warps of 64x64, BK=32, ping-pong smem.
// ---------------------------------------------------------------------------
extern "C" __global__ void __launch_bounds__(THREADS, 1)
fused_kernel(const float* __restrict__ x,
             const float* __restrict__ b1,
             const float* __restrict__ w2,
             const float* __restrict__ b2,
             float* __restrict__ out) {
    extern __shared__ __align__(128) char sm[];
    uint32_t smb = smem_u32(sm);

    int tid   = threadIdx.x;
    int warp  = tid >> 5;
    int lane  = tid & 31;
    int warpM = warp >> 2;               // 0..1 (64-row strips)
    int warpN = warp & 3;                // 0..3 (64-col strips)
    int rowBase = blockIdx.x * BM;

    float* s_out = reinterpret_cast<float*>(sm + SOUT_OFF);
    float* s_b1  = reinterpret_cast<float*>(sm + B1_OFF);
    float* s_w2  = reinterpret_cast<float*>(sm + W2_OFF);
    float* s_b2  = reinterpret_cast<float*>(sm + B2_OFF);

    // ---- epilogue constants + accumulator init ----
    for (int i = tid; i < NDIM; i += THREADS) s_b1[i] = b1[i];
    for (int i = tid; i < NDIM; i += THREADS) {
#pragma unroll
        for (int j = 0; j < OUTD; j++) s_w2[i * 12 + j] = w2[i * OUTD + j];
        s_w2[i * 12 + 10] = 0.f; s_w2[i * 12 + 11] = 0.f;
    }
    if (tid < 12) s_b2[tid] = (tid < OUTD) ? b2[tid] : 0.f;
    for (int i = tid; i < BM * 12; i += THREADS) s_out[i] = 0.f;

    wmma::fragment<wmma::accumulator, 16, 16, 16, float> acc[4][4];
#pragma unroll
    for (int mi = 0; mi < 4; mi++)
#pragma unroll
        for (int ni = 0; ni < 4; ni++)
            wmma::fill_fragment(acc[mi][ni], 0.0f);

    // loader mapping
    int xr = tid >> 1;               // 0..127
    int xc = (tid & 1) * 16;         // 0 or 16 (16 fp32 per thread)
    int wr = tid >> 3;               // 0..31
    int wc = (tid & 7) * 32;         // 0..224 (32 halfs = 64B per thread)

    const float* xptr = x + (size_t)(rowBase + xr) * KDIM + xc;
    const __half* whp = g_Wh + (size_t)wr * NDIM + wc;
    const __half* wlp = g_Wl + (size_t)wr * NDIM + wc;
    uint32_t wdst = smb + (uint32_t)(wr * WLD + wc) * 2;   // + WH/WL_OFF(buf)

    auto stage_x = [&](int buf, int k0) {
        __half hb[16];
        if (k0 + xc < KDIM) {      // full 16 valid (KDIM-768=16 ⇒ only k0=768,xc=16 invalid)
#pragma unroll
            for (int i = 0; i < 4; i++) {
                float4 v = *reinterpret_cast<const float4*>(xptr + k0 + i * 4);
                hb[i * 4 + 0] = __float2half_rn(v.x);
                hb[i * 4 + 1] = __float2half_rn(v.y);
                hb[i * 4 + 2] = __float2half_rn(v.z);
                hb[i * 4 + 3] = __float2half_rn(v.w);
            }
        } else {
#pragma unroll
            for (int i = 0; i < 16; i++) hb[i] = __float2half_rn(0.f);
        }
        uint4* dst = reinterpret_cast<uint4*>(sm + XH_OFF(buf) + (xr * XLD + xc) * 2);
        dst[0] = reinterpret_cast<uint4*>(hb)[0];
        dst[1] = reinterpret_cast<uint4*>(hb)[1];
    };
    auto issue_w = [&](int blk, int buf) {
        size_t off = (size_t)blk * BK * NDIM;
#pragma unroll
        for (int i = 0; i < 4; i++) {
            cp_async16(wdst + WH_OFF(buf) + i * 16, whp + off + i * 8);
            cp_async16(wdst + WL_OFF(buf) + i * 16, wlp + off + i * 8);
        }
        CP_COMMIT();
    };

    // ---- prologue: stage block 0 into buf 0 ----
    issue_w(0, 0);
    stage_x(0, 0);
    CP_WAIT0();
    __syncthreads();

    for (int it = 0; it < NITER; it++) {
        int cur = it & 1;
        int nxt = cur ^ 1;
        if (it + 1 < NITER) issue_w(it + 1, nxt);

        // ---- compute on current buffer: warp tile 64x64, 2 fp16 terms ----
        {
            const __half* xh = reinterpret_cast<const __half*>(sm + XH_OFF(cur));
            const __half* wh = reinterpret_cast<const __half*>(sm + WH_OFF(cur));
            const __half* wl = reinterpret_cast<const __half*>(sm + WL_OFF(cur));
#pragma unroll
            for (int ks = 0; ks < 2; ks++) {
                wmma::fragment<wmma::matrix_a, 16, 16, 16, __half, wmma::row_major> ah[4];
#pragma unroll
                for (int mi = 0; mi < 4; mi++)
                    wmma::load_matrix_sync(ah[mi],
                        xh + (warpM * 64 + mi * 16) * XLD + ks * 16, XLD);
#pragma unroll
                for (int ni = 0; ni < 4; ni++) {
                    wmma::fragment<wmma::matrix_b, 16, 16, 16, __half, wmma::row_major> bh, bl;
                    wmma::load_matrix_sync(bh, wh + (ks * 16) * WLD + warpN * 64 + ni * 16, WLD);
                    wmma::load_matrix_sync(bl, wl + (ks * 16) * WLD + warpN * 64 + ni * 16, WLD);
#pragma unroll
                    for (int mi = 0; mi < 4; mi++) {
                        wmma::mma_sync(acc[mi][ni], ah[mi], bh, acc[mi][ni]);
                        wmma::mma_sync(acc[mi][ni], ah[mi], bl, acc[mi][ni]);
                    }
                }
            }
        }

        if (it + 1 < NITER) {
            stage_x(nxt, (it + 1) * BK);
            CP_WAIT0();
        }
        __syncthreads();
    }

    // ======================= fused epilogue =======================
    // dec strips alias tile region (fully consumed after last sync): 8*1280B
    float* dec = reinterpret_cast<float*>(sm) + warp * (16 * DEC_LD);

    int rhalf = lane & 15;
    int chalf = (lane >> 4) * 8;
#pragma unroll
    for (int mi = 0; mi < 4; mi++) {
        int row = warpM * 64 + mi * 16 + rhalf;
        float p[12];
#pragma unroll
        for (int j = 0; j < 12; j++) p[j] = 0.f;
#pragma unroll
        for (int ni = 0; ni < 4; ni++) {
            wmma::store_matrix_sync(dec, acc[mi][ni], DEC_LD, wmma::mem_row_major);
            __syncwarp();
#pragma unroll
            for (int c = 0; c < 8; c++) {
                int n = warpN * 64 + ni * 16 + chalf + c;
                float v = dec[rhalf * DEC_LD + chalf + c] + s_b1[n];
                v = fmaxf(v, 0.f);
                const float4* wrp = reinterpret_cast<const float4*>(s_w2 + n * 12);
                float4 w0 = wrp[0], w1v = wrp[1], w2v = wrp[2];
                p[0]  += v * w0.x;  p[1]  += v * w0.y;  p[2]  += v * w0.z;  p[3]  += v * w0.w;
                p[4]  += v * w1v.x; p[5]  += v * w1v.y; p[6]  += v * w1v.z; p[7]  += v * w1v.w;
                p[8]  += v * w2v.x; p[9]  += v * w2v.y; p[10] += v * w2v.z; p[11] += v * w2v.w;
            }
            __syncwarp();
        }
#pragma unroll
        for (int j = 0; j < OUTD; j++)
            atomicAdd(&s_out[row * 12 + j], p[j]);
    }
    __syncthreads();

    // write out (+ b2)
    for (int i = tid; i < BM * OUTD; i += THREADS) {
        int r = i / OUTD, j = i - r * OUTD;
        out[(size_t)(rowBase + r) * OUTD + j] = s_out[r * 12 + j] + s_b2[j];
    }
}

// ---------------------------------------------------------------------------
extern "C" void kernel_launch(void* const* d_in, const int* in_sizes, int n_in,
                              void* d_out, int out_size) {
    const float* x      = (const float*)d_in[0];
    const float* w_conv = (const float*)d_in[1];
    const float* w1     = (const float*)d_in[2];
    const float* b1     = (const float*)d_in[3];
    const float* w2     = (const float*)d_in[4];
    const float* b2     = (const float*)d_in[5];
    float* out = (float*)d_out;

    cudaFuncSetAttribute(fused_kernel,
                         cudaFuncAttributeMaxDynamicSharedMemorySize, SMEM_BYTES);

    prep_kernel<<<KPAD, NDIM>>>(w_conv, w1);
    fused_kernel<<<BATCH / BM, THREADS, SMEM_BYTES>>>(x, b1, w2, b2, out);
}

// round 15
// speedup vs baseline: 2.1404x; 1.3219x over previous
#include <cuda_runtime.h>
#include <cuda_fp16.h>
#include <mma.h>
#include <cstdint>

using namespace nvcuda;

#define BATCH 65536
#define KDIM  784
#define KPAD  800           // 25 * 32, zero-padded weights
#define NDIM  256
#define OUTD  10

#define BM 128
#define BN 256
#define BK 32
#define NITER (KPAD / BK)   // 25
#define XLD 40              // x smem ld (elems), 80B rows
#define WLD 264             // w smem ld (elems), 528B rows
#define THREADS 256         // 8 warps: 2 (M) x 4 (N), warp tile 64x64
#define DEC_LD 20           // decode ld (80B)

// ---- smem layout (bytes) ----
#define XH_OFF(b) ((b) * 10240)             // 128*40*2
#define WH_OFF(b) (20480 + (b) * 16896)     // 32*264*2
#define SOUT_OFF  54272                     // 128*12 floats
#define B1_OFF    60416                     // 256 floats
#define W2_OFF    61440                     // 256*12 floats
#define B2_OFF    73728                     // 12 floats
#define SMEM_BYTES 73776

// Persistent weights (allocation-free rule: device globals), single fp16
__device__ __half g_Wh[KPAD * NDIM];

__device__ __forceinline__ uint32_t smem_u32(const void* p) {
    uint32_t a;
    asm("{ .reg .u64 t; cvta.to.shared.u64 t, %1; cvt.u32.u64 %0, t; }" : "=r"(a) : "l"(p));
    return a;
}
__device__ __forceinline__ void cp_async16(uint32_t dst, const void* src) {
    asm volatile("cp.async.ca.shared.global [%0], [%1], 16;" :: "r"(dst), "l"(src) : "memory");
}
#define CP_COMMIT() asm volatile("cp.async.commit_group;" ::: "memory")
#define CP_WAIT0()  asm volatile("cp.async.wait_group 0;" ::: "memory")

// ---------------------------------------------------------------------------
// prep: fold conv into W1_eff = C^T * w1, single fp16 (rows >= 784 zero)
// ---------------------------------------------------------------------------
__global__ void prep_kernel(const float* __restrict__ w_conv,
                            const float* __restrict__ w1) {
    int q = blockIdx.x;        // 0..799
    int n = threadIdx.x;       // 0..255
    float s = 0.f;
    if (q < KDIM) {
        int r = q / 28, c = q % 28;
#pragma unroll
        for (int i = 0; i < 3; i++) {
            int pr = r - i;
            if (pr < 0 || pr >= 26) continue;
#pragma unroll
            for (int j = 0; j < 3; j++) {
                int pc = c - j;
                if (pc < 0 || pc >= 26) continue;
                s += w_conv[i * 3 + j] * w1[(pr * 26 + pc) * NDIM + n];
            }
        }
    }
    g_Wh[q * NDIM + n] = __float2half_rn(s);
}

// ---------------------------------------------------------------------------
// Fused: out = relu(x @ W1_eff + b1) @ w2 + b2
// Single-term fp16 MMA (err ~3e-4), fp32 accumulate.
// CTA 128x256 (full N), 8 warps of 64x64, BK=32, ping-pong smem.
// ---------------------------------------------------------------------------
extern "C" __global__ void __launch_bounds__(THREADS, 1)
fused_kernel(const float* __restrict__ x,
             const float* __restrict__ b1,
             const float* __restrict__ w2,
             const float* __restrict__ b2,
             float* __restrict__ out) {
    extern __shared__ __align__(128) char sm[];
    uint32_t smb = smem_u32(sm);

    int tid   = threadIdx.x;
    int warp  = tid >> 5;
    int lane  = tid & 31;
    int warpM = warp >> 2;               // 0..1 (64-row strips)
    int warpN = warp & 3;                // 0..3 (64-col strips)
    int rowBase = blockIdx.x * BM;

    float* s_out = reinterpret_cast<float*>(sm + SOUT_OFF);
    float* s_b1  = reinterpret_cast<float*>(sm + B1_OFF);
    float* s_w2  = reinterpret_cast<float*>(sm + W2_OFF);
    float* s_b2  = reinterpret_cast<float*>(sm + B2_OFF);

    // ---- epilogue constants + accumulator init ----
    for (int i = tid; i < NDIM; i += THREADS) s_b1[i] = b1[i];
    for (int i = tid; i < NDIM; i += THREADS) {
#pragma unroll
        for (int j = 0; j < OUTD; j++) s_w2[i * 12 + j] = w2[i * OUTD + j];
        s_w2[i * 12 + 10] = 0.f; s_w2[i * 12 + 11] = 0.f;
    }
    if (tid < 12) s_b2[tid] = (tid < OUTD) ? b2[tid] : 0.f;
    for (int i = tid; i < BM * 12; i += THREADS) s_out[i] = 0.f;

    wmma::fragment<wmma::accumulator, 16, 16, 16, float> acc[4][4];
#pragma unroll
    for (int mi = 0; mi < 4; mi++)
#pragma unroll
        for (int ni = 0; ni < 4; ni++)
            wmma::fill_fragment(acc[mi][ni], 0.0f);

    // loader mapping
    int xr = tid >> 1;               // 0..127
    int xc = (tid & 1) * 16;         // 0 or 16 (16 fp32 per thread)
    int wr = tid >> 3;               // 0..31
    int wc = (tid & 7) * 32;         // 0..224 (32 halfs = 64B per thread)

    const float* xptr = x + (size_t)(rowBase + xr) * KDIM + xc;
    const __half* whp = g_Wh + (size_t)wr * NDIM + wc;
    uint32_t wdst = smb + (uint32_t)(wr * WLD + wc) * 2;   // + WH_OFF(buf)

    auto stage_x = [&](int buf, int k0) {
        __half hb[16];
        if (k0 + xc < KDIM) {      // only k0=768,xc=16 chunk is fully OOB
#pragma unroll
            for (int i = 0; i < 4; i++) {
                float4 v = *reinterpret_cast<const float4*>(xptr + k0 + i * 4);
                hb[i * 4 + 0] = __float2half_rn(v.x);
                hb[i * 4 + 1] = __float2half_rn(v.y);
                hb[i * 4 + 2] = __float2half_rn(v.z);
                hb[i * 4 + 3] = __float2half_rn(v.w);
            }
        } else {
#pragma unroll
            for (int i = 0; i < 16; i++) hb[i] = __float2half_rn(0.f);
        }
        uint4* dst = reinterpret_cast<uint4*>(sm + XH_OFF(buf) + (xr * XLD + xc) * 2);
        dst[0] = reinterpret_cast<uint4*>(hb)[0];
        dst[1] = reinterpret_cast<uint4*>(hb)[1];
    };
    auto issue_w = [&](int blk, int buf) {
        size_t off = (size_t)blk * BK * NDIM;
#pragma unroll
        for (int i = 0; i < 4; i++)
            cp_async16(wdst + WH_OFF(buf) + i * 16, whp + off + i * 8);
        CP_COMMIT();
    };

    // ---- prologue: stage block 0 into buf 0 ----
    issue_w(0, 0);
    stage_x(0, 0);
    CP_WAIT0();
    __syncthreads();

    for (int it = 0; it < NITER; it++) {
        int cur = it & 1;
        int nxt = cur ^ 1;
        if (it + 1 < NITER) issue_w(it + 1, nxt);

        // ---- compute on current buffer: warp tile 64x64, single term ----
        {
            const __half* xh = reinterpret_cast<const __half*>(sm + XH_OFF(cur));
            const __half* wh = reinterpret_cast<const __half*>(sm + WH_OFF(cur));
#pragma unroll
            for (int ks = 0; ks < 2; ks++) {
                wmma::fragment<wmma::matrix_a, 16, 16, 16, __half, wmma::row_major> ah[4];
#pragma unroll
                for (int mi = 0; mi < 4; mi++)
                    wmma::load_matrix_sync(ah[mi],
                        xh + (warpM * 64 + mi * 16) * XLD + ks * 16, XLD);
#pragma unroll
                for (int ni = 0; ni < 4; ni++) {
                    wmma::fragment<wmma::matrix_b, 16, 16, 16, __half, wmma::row_major> bh;
                    wmma::load_matrix_sync(bh, wh + (ks * 16) * WLD + warpN * 64 + ni * 16, WLD);
#pragma unroll
                    for (int mi = 0; mi < 4; mi++)
                        wmma::mma_sync(acc[mi][ni], ah[mi], bh, acc[mi][ni]);
                }
            }
        }

        if (it + 1 < NITER) {
            stage_x(nxt, (it + 1) * BK);
            CP_WAIT0();
        }
        __syncthreads();
    }

    // ======================= fused epilogue =======================
    // dec strips alias tile region (fully consumed after last sync): 8*1280B
    float* dec = reinterpret_cast<float*>(sm) + warp * (16 * DEC_LD);

    int rhalf = lane & 15;
    int chalf = (lane >> 4) * 8;
#pragma unroll
    for (int mi = 0; mi < 4; mi++) {
        int row = warpM * 64 + mi * 16 + rhalf;
        float p[12];
#pragma unroll
        for (int j = 0; j < 12; j++) p[j] = 0.f;
#pragma unroll
        for (int ni = 0; ni < 4; ni++) {
            wmma::store_matrix_sync(dec, acc[mi][ni], DEC_LD, wmma::mem_row_major);
            __syncwarp();
#pragma unroll
            for (int c = 0; c < 8; c++) {
                int n = warpN * 64 + ni * 16 + chalf + c;
                float v = dec[rhalf * DEC_LD + chalf + c] + s_b1[n];
                v = fmaxf(v, 0.f);
                const float4* wrp = reinterpret_cast<const float4*>(s_w2 + n * 12);
                float4 w0 = wrp[0], w1v = wrp[1], w2v = wrp[2];
                p[0]  += v * w0.x;  p[1]  += v * w0.y;  p[2]  += v * w0.z;  p[3]  += v * w0.w;
                p[4]  += v * w1v.x; p[5]  += v * w1v.y; p[6]  += v * w1v.z; p[7]  += v * w1v.w;
                p[8]  += v * w2v.x; p[9]  += v * w2v.y; p[10] += v * w2v.z; p[11] += v * w2v.w;
            }
            __syncwarp();
        }
#pragma unroll
        for (int j = 0; j < OUTD; j++)
            atomicAdd(&s_out[row * 12 + j], p[j]);
    }
    __syncthreads();

    // write out (+ b2)
    for (int i = tid; i < BM * OUTD; i += THREADS) {
        int r = i / OUTD, j = i - r * OUTD;
        out[(size_t)(rowBase + r) * OUTD + j] = s_out[r * 12 + j] + s_b2[j];
    }
}

// ---------------------------------------------------------------------------
extern "C" void kernel_launch(void* const* d_in, const int* in_sizes, int n_in,
                              void* d_out, int out_size) {
    const float* x      = (const float*)d_in[0];
    const float* w_conv = (const float*)d_in[1];
    const float* w1     = (const float*)d_in[2];
    const float* b1     = (const float*)d_in[3];
    const float* w2     = (const float*)d_in[4];
    const float* b2     = (const float*)d_in[5];
    float* out = (float*)d_out;

    cudaFuncSetAttribute(fused_kernel,
                         cudaFuncAttributeMaxDynamicSharedMemorySize, SMEM_BYTES);

    prep_kernel<<<KPAD, NDIM>>>(w_conv, w1);
    fused_kernel<<<BATCH / BM, THREADS, SMEM_BYTES>>>(x, b1, w2, b2, out);
}